// round 7
// baseline (speedup 1.0000x reference)
#include <cuda_runtime.h>
#include <math.h>
#include <stdint.h>

// N=50000, P=1.6M, F=128, G=16, H=32, HID1=256, HID2=128, IN=288 (vec_q==0 dropped)
#define NMAX 50000

__device__ float g_acc[NMAX * 64];            // [n][0:16]=Gsum, [16:64]=GVsum(d,g)
__device__ float g_msg[(size_t)NMAX * 288];   // MLP input, tf32-rounded
__device__ float g_embT[(size_t)NMAX * 128];  // emb tf32
__device__ float g_aghT[128 * 512];           // agh tf32
__device__ float g_w1t[288 * 256];            // W1 tf32
__device__ float g_w2t[256 * 128];            // W2 tf32
__device__ float g_w3t[128 * 136];            // W3 tf32, cols padded 130->136 (zeros)

__device__ __forceinline__ float gelu_exact(float x) {
    return 0.5f * x * (1.0f + erff(x * 0.70710678118654752f));
}
__device__ __forceinline__ float f2tf(float x) {
    uint32_t r;
    asm("cvt.rna.tf32.f32 %0, %1;" : "=r"(r) : "f"(x));
    return __uint_as_float(r);
}
__device__ __forceinline__ void mma_tf32(float d[4], const uint32_t a[4],
                                         const uint32_t b[2]) {
    asm volatile(
        "mma.sync.aligned.m16n8k8.row.col.f32.tf32.tf32.f32 "
        "{%0,%1,%2,%3}, {%4,%5,%6,%7}, {%8,%9}, {%0,%1,%2,%3};"
        : "+f"(d[0]), "+f"(d[1]), "+f"(d[2]), "+f"(d[3])
        : "r"(a[0]), "r"(a[1]), "r"(a[2]), "r"(a[3]), "r"(b[0]), "r"(b[1]));
}
__device__ __forceinline__ uint32_t fu(float x) { return __float_as_uint(x); }

__device__ __forceinline__ void cpa16(float* s, const float* g) {
    uint32_t sp = (uint32_t)__cvta_generic_to_shared(s);
    asm volatile("cp.async.cg.shared.global [%0], [%1], 16;" :: "r"(sp), "l"(g));
}
#define CP_COMMIT() asm volatile("cp.async.commit_group;" ::: "memory")
#define CP_WAIT1()  asm volatile("cp.async.wait_group 1;" ::: "memory")

// ---------------------------------------------------------------------------
// Launch 1: tf32 pre-conversion (weights + emb) AND zero pair accumulators
// ---------------------------------------------------------------------------
#define CVT_W (128 * 512 + 288 * 256 + 256 * 128 + 128 * 136)
__global__ void k_cvt(const float* __restrict__ agh, const float* __restrict__ W1,
                      const float* __restrict__ W2, const float* __restrict__ W3,
                      const float* __restrict__ emb, int N) {
    int i = blockIdx.x * blockDim.x + threadIdx.x;
    if (i < 128 * 512) { g_aghT[i] = f2tf(agh[i]); return; }
    i -= 128 * 512;
    if (i < 288 * 256) { g_w1t[i] = f2tf(W1[i]); return; }
    i -= 288 * 256;
    if (i < 256 * 128) { g_w2t[i] = f2tf(W2[i]); return; }
    i -= 256 * 128;
    if (i < 128 * 136) {
        int r = i / 136, c = i - r * 136;
        g_w3t[i] = (c < 130) ? f2tf(W3[r * 130 + c]) : 0.f;
        return;
    }
    i -= 128 * 136;
    if (i < N * 32) {   // float4 granularity over emb
        float4 v = reinterpret_cast<const float4*>(emb)[i];
        float4 o = make_float4(f2tf(v.x), f2tf(v.y), f2tf(v.z), f2tf(v.w));
        reinterpret_cast<float4*>(g_embT)[i] = o;
        return;
    }
    i -= N * 32;
    if (i < N * 16)     // zero g_acc (float4)
        reinterpret_cast<float4*>(g_acc)[i] = make_float4(0.f, 0.f, 0.f, 0.f);
}

// ---------------------------------------------------------------------------
// Launch 2: scatter gs(16)+gv(48) per pair via red.global.add.v4 (unchanged)
// ---------------------------------------------------------------------------
__global__ void k_scatter(const int* __restrict__ idxj, const float* __restrict__ gs,
                          const float* __restrict__ gv, int P) {
    long long q = (long long)blockIdx.x * blockDim.x + threadIdx.x;
    long long total = (long long)P * 16;
    if (q >= total) return;
    int p = (int)(q >> 4);
    int c = (int)(q & 15);
    int n = idxj[p];
    float4 v;
    float* dst;
    if (c < 4) {
        v = *reinterpret_cast<const float4*>(gs + (size_t)p * 16 + c * 4);
        dst = g_acc + (size_t)n * 64 + c * 4;
    } else {
        v = *reinterpret_cast<const float4*>(gv + (size_t)p * 48 + (c - 4) * 4);
        dst = g_acc + (size_t)n * 64 + 16 + (c - 4) * 4;
    }
    asm volatile("red.global.add.v4.f32 [%0], {%1,%2,%3,%4};"
                 :: "l"(dst), "f"(v.x), "f"(v.y), "f"(v.z), "f"(v.w)
                 : "memory");
}

// ---------------------------------------------------------------------------
// Launch 3: fused GEMM-M + assemble (unchanged from R6).
// ---------------------------------------------------------------------------
#define XSF 132
#define WSC 520
#define MSF 516
#define OXS 0
#define OSA 4224
#define OWG 6272
#define OWB 8320
#define GA_SMEM (24960 * 4)           // 99840 B

__global__ void __launch_bounds__(256, 2) k_gemm_assemble(
    const float* __restrict__ q, const float* __restrict__ Wgf, int N) {
    extern __shared__ float sm[];
    float* Xs   = sm + OXS;
    float* sa   = sm + OSA;
    float* Wgfs = sm + OWG;
    float* Wb0  = sm + OWB;
    float* Wb1  = sm + OWB + 8320;
    float* Ms   = sm + OWB;            // overlays Wb0+Wb1 after MMA
    int a0 = blockIdx.x * 32;
    int tid = threadIdx.x;
    int lane = tid & 31, wn = tid >> 5;
    int gid = lane >> 2, tig = lane & 3;

    for (int i = tid; i < 32 * 32; i += 256) {
        int r = i >> 5, f4 = i & 31;
        int n = a0 + r; if (n >= N) n = N - 1;
        cpa16(Xs + r * XSF + f4 * 4, g_embT + (size_t)n * 128 + f4 * 4);
    }
    for (int i = tid; i < 32 * 16; i += 256) {
        int r = i >> 4, c4 = i & 15;
        int n = a0 + r; if (n >= N) n = N - 1;
        cpa16(sa + r * 64 + c4 * 4, g_acc + (size_t)n * 64 + c4 * 4);
    }
    for (int i = tid; i < 16 * 32; i += 256) {
        cpa16(Wgfs + i * 4, Wgf + i * 4);
    }
    for (int i = tid; i < 16 * 128; i += 256) {
        int r = i >> 7, c4 = i & 127;
        cpa16(Wb0 + r * WSC + c4 * 4, g_aghT + (size_t)r * 512 + c4 * 4);
    }
    CP_COMMIT();
    for (int i = tid; i < 16 * 128; i += 256) {
        int r = i >> 7, c4 = i & 127;
        cpa16(Wb1 + r * WSC + c4 * 4, g_aghT + (size_t)(16 + r) * 512 + c4 * 4);
    }
    CP_COMMIT();

    float acc[2][8][4];
    #pragma unroll
    for (int mt = 0; mt < 2; mt++)
        #pragma unroll
        for (int nt = 0; nt < 8; nt++)
            #pragma unroll
            for (int e = 0; e < 4; e++) acc[mt][nt][e] = 0.f;

    for (int c = 0; c < 8; c++) {
        CP_WAIT1();
        __syncthreads();
        float* wb = (c & 1) ? Wb1 : Wb0;
        #pragma unroll
        for (int ks = 0; ks < 16; ks += 8) {
            int kg = c * 16 + ks;
            uint32_t A[2][4];
            #pragma unroll
            for (int mt = 0; mt < 2; mt++) {
                int row = 16 * mt + gid;
                A[mt][0] = fu(Xs[row * XSF + kg + tig]);
                A[mt][1] = fu(Xs[(row + 8) * XSF + kg + tig]);
                A[mt][2] = fu(Xs[row * XSF + kg + tig + 4]);
                A[mt][3] = fu(Xs[(row + 8) * XSF + kg + tig + 4]);
            }
            #pragma unroll
            for (int nt = 0; nt < 8; nt++) {
                int col = 64 * wn + 8 * nt + gid;
                uint32_t B[2];
                B[0] = fu(wb[(ks + tig) * WSC + col]);
                B[1] = fu(wb[(ks + tig + 4) * WSC + col]);
                mma_tf32(acc[0][nt], A[0], B);
                mma_tf32(acc[1][nt], A[1], B);
            }
        }
        __syncthreads();
        if (c + 2 < 8) {
            float* dst = (c & 1) ? Wb1 : Wb0;
            for (int i = tid; i < 16 * 128; i += 256) {
                int r = i >> 7, c4 = i & 127;
                cpa16(dst + r * WSC + c4 * 4,
                      g_aghT + (size_t)((c + 2) * 16 + r) * 512 + c4 * 4);
            }
        }
        CP_COMMIT();
    }

    #pragma unroll
    for (int mt = 0; mt < 2; mt++) {
        int r0 = 16 * mt + gid;
        #pragma unroll
        for (int nt = 0; nt < 8; nt++) {
            int col = 64 * wn + 8 * nt + 2 * tig;
            *reinterpret_cast<float2*>(&Ms[r0 * MSF + col]) =
                make_float2(acc[mt][nt][0], acc[mt][nt][1]);
            *reinterpret_cast<float2*>(&Ms[(r0 + 8) * MSF + col]) =
                make_float2(acc[mt][nt][2], acc[mt][nt][3]);
        }
    }
    __syncthreads();

    for (int idx = tid; idx < 32 * 128; idx += 256) {
        int r = idx >> 7, f = idx & 127;
        int n = a0 + r;
        if (n >= N) continue;
        float m = 0.f;
        #pragma unroll
        for (int g = 0; g < 16; g++) m += sa[r * 64 + g] * Wgfs[g * 128 + f];
        float* msg = g_msg + (size_t)n * 288;
        msg[f]       = f2tf(Xs[r * XSF + f] * m);
        msg[160 + f] = f2tf(q[n] * m);
    }
    for (int idx = tid; idx < 32 * 32; idx += 256) {
        int r = idx >> 5, h = idx & 31;
        int n = a0 + r;
        if (n >= N) continue;
        float v0 = 0.f, v1 = 0.f, v2 = 0.f;
        #pragma unroll
        for (int g = 0; g < 16; g++) {
            float Mv = Ms[r * MSF + g * 32 + h];
            v0 += sa[r * 64 + 16 + g] * Mv;
            v1 += sa[r * 64 + 32 + g] * Mv;
            v2 += sa[r * 64 + 48 + g] * Mv;
        }
        float sq = v0 * v0 + v1 * v1 + v2 * v2;
        g_msg[(size_t)n * 288 + 128 + h] = (sq > 0.f) ? f2tf(sqrtf(sq)) : 0.f;
    }
}

// ---------------------------------------------------------------------------
// Launch 4 (PROFILED): fused 3-layer MLP, 32 atoms/CTA, 16-row weight chunks,
// cp.async double-buffered. smem 88064 B -> 2 CTAs/SM.
// ---------------------------------------------------------------------------
#define XSP 292
#define H1P 260
#define H2P 132
#define W1P 264
#define W2P 136
#define W3P 136
#define MWB 4224                       // 16*264 floats per weight buffer
#define MOX 0                          // Xs/H1: 32*292 = 9344
#define MW0 9344
#define MW1 (9344 + MWB)               // 13568
#define MH2 (13568 + MWB)              // 17792
#define MLP_SMEM ((17792 + 32 * H2P) * 4)   // 88064 B

__global__ void __launch_bounds__(256, 2) k_mlp_tc(
    const float* __restrict__ b1, const float* __restrict__ b2,
    const float* __restrict__ b3, float* __restrict__ out, int N) {
    extern __shared__ float sm[];
    float* Xs  = sm + MOX;
    float* H1  = sm + MOX;
    float* Wb0 = sm + MW0;
    float* Wb1 = sm + MW1;
    float* H2  = sm + MH2;
    int a0 = blockIdx.x * 32;
    int tid = threadIdx.x;
    int lane = tid & 31, warp = tid >> 5;
    int gid = lane >> 2, tig = lane & 3;
    // 8 warps: layer1 each warp owns 32 cols (4 n-tiles), all 32 rows (2 m-tiles)

    // prologue: Xs + W1 chunk0 -> group0 ; W1 chunk1 -> group1
    for (int i = tid; i < 32 * 72; i += 256) {
        int r = i / 72, k4 = i - r * 72;
        int n = a0 + r; if (n >= N) n = N - 1;
        cpa16(Xs + r * XSP + k4 * 4, g_msg + (size_t)n * 288 + k4 * 4);
    }
    for (int i = tid; i < 16 * 64; i += 256) {
        int r = i >> 6, c4 = i & 63;
        cpa16(Wb0 + r * W1P + c4 * 4, g_w1t + (size_t)r * 256 + c4 * 4);
    }
    CP_COMMIT();
    for (int i = tid; i < 16 * 64; i += 256) {
        int r = i >> 6, c4 = i & 63;
        cpa16(Wb1 + r * W1P + c4 * 4, g_w1t + (size_t)(16 + r) * 256 + c4 * 4);
    }
    CP_COMMIT();

    // ============ Layer 1: 288 -> 256, gelu (18 chunks of 16) ============
    float acc1[2][4][4];
    #pragma unroll
    for (int mt = 0; mt < 2; mt++)
        #pragma unroll
        for (int nt = 0; nt < 4; nt++)
            #pragma unroll
            for (int e = 0; e < 4; e++) acc1[mt][nt][e] = 0.f;

    for (int c = 0; c < 18; c++) {
        CP_WAIT1();
        __syncthreads();
        float* wb = (c & 1) ? Wb1 : Wb0;
        #pragma unroll
        for (int ks = 0; ks < 16; ks += 8) {
            int kg = c * 16 + ks;
            uint32_t A[2][4];
            #pragma unroll
            for (int mt = 0; mt < 2; mt++) {
                int row = 16 * mt + gid;
                A[mt][0] = fu(Xs[row * XSP + kg + tig]);
                A[mt][1] = fu(Xs[(row + 8) * XSP + kg + tig]);
                A[mt][2] = fu(Xs[row * XSP + kg + tig + 4]);
                A[mt][3] = fu(Xs[(row + 8) * XSP + kg + tig + 4]);
            }
            #pragma unroll
            for (int nt = 0; nt < 4; nt++) {
                int col = 32 * warp + 8 * nt + gid;
                uint32_t B[2];
                B[0] = fu(wb[(ks + tig) * W1P + col]);
                B[1] = fu(wb[(ks + tig + 4) * W1P + col]);
                mma_tf32(acc1[0][nt], A[0], B);
                mma_tf32(acc1[1][nt], A[1], B);
            }
        }
        __syncthreads();
        if (c + 2 < 18) {
            float* dst = (c & 1) ? Wb1 : Wb0;
            for (int i = tid; i < 16 * 64; i += 256) {
                int r = i >> 6, c4 = i & 63;
                cpa16(dst + r * W1P + c4 * 4,
                      g_w1t + (size_t)((c + 2) * 16 + r) * 256 + c4 * 4);
            }
        }
        CP_COMMIT();
    }

    // prefetch W2 chunks 0,1
    for (int i = tid; i < 16 * 32; i += 256) {
        int r = i >> 5, c4 = i & 31;
        cpa16(Wb0 + r * W2P + c4 * 4, g_w2t + (size_t)r * 128 + c4 * 4);
    }
    CP_COMMIT();
    for (int i = tid; i < 16 * 32; i += 256) {
        int r = i >> 5, c4 = i & 31;
        cpa16(Wb1 + r * W2P + c4 * 4, g_w2t + (size_t)(16 + r) * 128 + c4 * 4);
    }
    CP_COMMIT();

    // H1 epilogue (Xs reads done; overwrite region)
    #pragma unroll
    for (int mt = 0; mt < 2; mt++) {
        int r0 = 16 * mt + gid;
        #pragma unroll
        for (int nt = 0; nt < 4; nt++) {
            int col = 32 * warp + 8 * nt + 2 * tig;
            float bb0 = b1[col], bb1 = b1[col + 1];
            H1[r0 * H1P + col]     = f2tf(gelu_exact(acc1[mt][nt][0] + bb0));
            H1[r0 * H1P + col + 1] = f2tf(gelu_exact(acc1[mt][nt][1] + bb1));
            H1[(r0 + 8) * H1P + col]     = f2tf(gelu_exact(acc1[mt][nt][2] + bb0));
            H1[(r0 + 8) * H1P + col + 1] = f2tf(gelu_exact(acc1[mt][nt][3] + bb1));
        }
    }
    __syncthreads();

    // ============ Layer 2: 256 -> 128, gelu (16 chunks of 16) ============
    float acc2[2][2][4];
    #pragma unroll
    for (int mt = 0; mt < 2; mt++)
        #pragma unroll
        for (int nt = 0; nt < 2; nt++)
            #pragma unroll
            for (int e = 0; e < 4; e++) acc2[mt][nt][e] = 0.f;

    for (int c = 0; c < 16; c++) {
        CP_WAIT1();
        __syncthreads();
        float* wb = (c & 1) ? Wb1 : Wb0;
        #pragma unroll
        for (int ks = 0; ks < 16; ks += 8) {
            int kg = c * 16 + ks;
            uint32_t A[2][4];
            #pragma unroll
            for (int mt = 0; mt < 2; mt++) {
                int row = 16 * mt + gid;
                A[mt][0] = fu(H1[row * H1P + kg + tig]);
                A[mt][1] = fu(H1[(row + 8) * H1P + kg + tig]);
                A[mt][2] = fu(H1[row * H1P + kg + tig + 4]);
                A[mt][3] = fu(H1[(row + 8) * H1P + kg + tig + 4]);
            }
            #pragma unroll
            for (int nt = 0; nt < 2; nt++) {
                int col = 16 * warp + 8 * nt + gid;
                uint32_t B[2];
                B[0] = fu(wb[(ks + tig) * W2P + col]);
                B[1] = fu(wb[(ks + tig + 4) * W2P + col]);
                mma_tf32(acc2[0][nt], A[0], B);
                mma_tf32(acc2[1][nt], A[1], B);
            }
        }
        __syncthreads();
        if (c + 2 < 16) {
            float* dst = (c & 1) ? Wb1 : Wb0;
            for (int i = tid; i < 16 * 32; i += 256) {
                int r = i >> 5, c4 = i & 31;
                cpa16(dst + r * W2P + c4 * 4,
                      g_w2t + (size_t)((c + 2) * 16 + r) * 128 + c4 * 4);
            }
        }
        CP_COMMIT();
    }

    // prefetch W3 chunks 0,1
    for (int i = tid; i < 16 * 34; i += 256) {
        int r = i / 34, c4 = i - r * 34;
        cpa16(Wb0 + r * W3P + c4 * 4, g_w3t + (size_t)r * 136 + c4 * 4);
    }
    CP_COMMIT();
    for (int i = tid; i < 16 * 34; i += 256) {
        int r = i / 34, c4 = i - r * 34;
        cpa16(Wb1 + r * W3P + c4 * 4, g_w3t + (size_t)(16 + r) * 136 + c4 * 4);
    }
    CP_COMMIT();

    // H2 epilogue
    #pragma unroll
    for (int mt = 0; mt < 2; mt++) {
        int r0 = 16 * mt + gid;
        #pragma unroll
        for (int nt = 0; nt < 2; nt++) {
            int col = 16 * warp + 8 * nt + 2 * tig;
            float bb0 = b2[col], bb1 = b2[col + 1];
            H2[r0 * H2P + col]     = f2tf(gelu_exact(acc2[mt][nt][0] + bb0));
            H2[r0 * H2P + col + 1] = f2tf(gelu_exact(acc2[mt][nt][1] + bb1));
            H2[(r0 + 8) * H2P + col]     = f2tf(gelu_exact(acc2[mt][nt][2] + bb0));
            H2[(r0 + 8) * H2P + col + 1] = f2tf(gelu_exact(acc2[mt][nt][3] + bb1));
        }
    }
    __syncthreads();

    // ============ Layer 3: 128 -> 130(136), linear (8 chunks of 16) =========
    // 34 warp-tiles (2 m x 17 n), round-robin over 8 warps (up to 5 each)
    float d3[5][4];
    #pragma unroll
    for (int tt = 0; tt < 5; tt++)
        #pragma unroll
        for (int e = 0; e < 4; e++) d3[tt][e] = 0.f;

    for (int c = 0; c < 8; c++) {
        CP_WAIT1();
        __syncthreads();
        float* wb = (c & 1) ? Wb1 : Wb0;
        #pragma unroll
        for (int tt = 0; tt < 5; tt++) {
            int t = warp + 8 * tt;
            if (t >= 34) break;
            int m0 = 16 * (t & 1), n0 = 8 * (t >> 1);
            #pragma unroll
            for (int ks = 0; ks < 16; ks += 8) {
                int kg = c * 16 + ks;
                uint32_t A[4], B[2];
                A[0] = fu(H2[(m0 + gid) * H2P + kg + tig]);
                A[1] = fu(H2[(m0 + 8 + gid) * H2P + kg + tig]);
                A[2] = fu(H2[(m0 + gid) * H2P + kg + tig + 4]);
                A[3] = fu(H2[(m0 + 8 + gid) * H2P + kg + tig + 4]);
                B[0] = fu(wb[(ks + tig) * W3P + n0 + gid]);
                B[1] = fu(wb[(ks + tig + 4) * W3P + n0 + gid]);
                mma_tf32(d3[tt], A, B);
            }
        }
        __syncthreads();
        if (c + 2 < 8) {
            float* dst = (c & 1) ? Wb1 : Wb0;
            for (int i = tid; i < 16 * 34; i += 256) {
                int r = i / 34, c4 = i - r * 34;
                cpa16(dst + r * W3P + c4 * 4,
                      g_w3t + (size_t)((c + 2) * 16 + r) * 136 + c4 * 4);
            }
        }
        CP_COMMIT();
    }

    // store
    size_t dq_off = (size_t)N * 128;
    size_t f_off = dq_off + (size_t)N;
    #pragma unroll
    for (int tt = 0; tt < 5; tt++) {
        int t = warp + 8 * tt;
        if (t >= 34) break;
        int m0 = 16 * (t & 1), n0 = 8 * (t >> 1);
        #pragma unroll
        for (int e = 0; e < 4; e++) {
            int r = m0 + gid + ((e >> 1) ? 8 : 0);
            int j = n0 + 2 * tig + (e & 1);
            int n = a0 + r;
            if (n >= N || j >= 130) continue;
            float v = d3[tt][e] + b3[j];
            if (j == 0)      out[dq_off + n] = v;
            else if (j == 1) out[f_off + n] = v;
            else             out[(size_t)n * 128 + (j - 2)] = v;
        }
    }
}

// ---------------------------------------------------------------------------
extern "C" void kernel_launch(void* const* d_in, const int* in_sizes, int n_in,
                              void* d_out, int out_size) {
    const float* emb  = (const float*)d_in[0];
    const float* q    = (const float*)d_in[1];
    const int*   pidx = (const int*)d_in[2];
    const float* gs   = (const float*)d_in[3];
    const float* gv   = (const float*)d_in[4];
    const float* agh  = (const float*)d_in[5];
    const float* Wgf  = (const float*)d_in[6];
    const float* W1   = (const float*)d_in[7];
    const float* b1   = (const float*)d_in[8];
    const float* W2   = (const float*)d_in[9];
    const float* b2   = (const float*)d_in[10];
    const float* W3   = (const float*)d_in[11];
    const float* b3   = (const float*)d_in[12];
    float* out = (float*)d_out;

    int N = in_sizes[0] / 128;
    int P = in_sizes[2] / 2;
    if (N > NMAX) N = NMAX;
    const int* idxj = pidx + P;

    // 1: tf32 conversion + zero accumulators (merged)
    int cvt_tot = CVT_W + N * 32 + N * 16;
    k_cvt<<<(cvt_tot + 255) / 256, 256>>>(agh, W1, W2, W3, emb, N);

    // 2: pair scatter
    long long Q = (long long)P * 16;
    k_scatter<<<(int)((Q + 255) / 256), 256>>>(idxj, gs, gv, P);

    // 3: fused GEMM-M + assemble
    cudaFuncSetAttribute(k_gemm_assemble, cudaFuncAttributeMaxDynamicSharedMemorySize, GA_SMEM);
    k_gemm_assemble<<<(N + 31) / 32, 256, GA_SMEM>>>(q, Wgf, N);

    // 4 (profiled): fused MLP, 2 CTAs/SM
    cudaFuncSetAttribute(k_mlp_tc, cudaFuncAttributeMaxDynamicSharedMemorySize, MLP_SMEM);
    k_mlp_tc<<<(N + 31) / 32, 256, MLP_SMEM>>>(b1, b2, b3, out, N);
}

// round 8
// speedup vs baseline: 1.0062x; 1.0062x over previous
#include <cuda_runtime.h>
#include <math.h>
#include <stdint.h>

// N=50000, P=1.6M, F=128, G=16, H=32, HID1=256, HID2=128, IN=288 (vec_q==0 dropped)
#define NMAX 50000

__device__ float g_acc[NMAX * 64];            // [n][0:16]=Gsum, [16:64]=GVsum(d,g)
__device__ float g_msg[(size_t)NMAX * 288];   // MLP input, tf32-rounded
__device__ float g_embT[(size_t)NMAX * 128];  // emb tf32
__device__ float g_aghT[128 * 512];           // agh tf32
__device__ float g_w1t[288 * 256];            // W1 tf32
__device__ float g_w2t[256 * 128];            // W2 tf32
__device__ float g_w3t[128 * 136];            // W3 tf32, cols padded 130->136 (zeros)

__device__ __forceinline__ float gelu_exact(float x) {
    return 0.5f * x * (1.0f + erff(x * 0.70710678118654752f));
}
__device__ __forceinline__ float f2tf(float x) {
    uint32_t r;
    asm("cvt.rna.tf32.f32 %0, %1;" : "=r"(r) : "f"(x));
    return __uint_as_float(r);
}
__device__ __forceinline__ void mma_tf32(float d[4], const uint32_t a[4],
                                         const uint32_t b[2]) {
    asm volatile(
        "mma.sync.aligned.m16n8k8.row.col.f32.tf32.tf32.f32 "
        "{%0,%1,%2,%3}, {%4,%5,%6,%7}, {%8,%9}, {%0,%1,%2,%3};"
        : "+f"(d[0]), "+f"(d[1]), "+f"(d[2]), "+f"(d[3])
        : "r"(a[0]), "r"(a[1]), "r"(a[2]), "r"(a[3]), "r"(b[0]), "r"(b[1]));
}
__device__ __forceinline__ uint32_t fu(float x) { return __float_as_uint(x); }

__device__ __forceinline__ void cpa16(float* s, const float* g) {
    uint32_t sp = (uint32_t)__cvta_generic_to_shared(s);
    asm volatile("cp.async.cg.shared.global [%0], [%1], 16;" :: "r"(sp), "l"(g));
}
#define CP_COMMIT() asm volatile("cp.async.commit_group;" ::: "memory")
#define CP_WAIT1()  asm volatile("cp.async.wait_group 1;" ::: "memory")

// ---------------------------------------------------------------------------
// Launch 1: tf32 pre-conversion (weights + emb) AND zero pair accumulators
// ---------------------------------------------------------------------------
#define CVT_W (128 * 512 + 288 * 256 + 256 * 128 + 128 * 136)
__global__ void k_cvt(const float* __restrict__ agh, const float* __restrict__ W1,
                      const float* __restrict__ W2, const float* __restrict__ W3,
                      const float* __restrict__ emb, int N) {
    int i = blockIdx.x * blockDim.x + threadIdx.x;
    if (i < 128 * 512) { g_aghT[i] = f2tf(agh[i]); return; }
    i -= 128 * 512;
    if (i < 288 * 256) { g_w1t[i] = f2tf(W1[i]); return; }
    i -= 288 * 256;
    if (i < 256 * 128) { g_w2t[i] = f2tf(W2[i]); return; }
    i -= 256 * 128;
    if (i < 128 * 136) {
        int r = i / 136, c = i - r * 136;
        g_w3t[i] = (c < 130) ? f2tf(W3[r * 130 + c]) : 0.f;
        return;
    }
    i -= 128 * 136;
    if (i < N * 32) {
        float4 v = reinterpret_cast<const float4*>(emb)[i];
        float4 o = make_float4(f2tf(v.x), f2tf(v.y), f2tf(v.z), f2tf(v.w));
        reinterpret_cast<float4*>(g_embT)[i] = o;
        return;
    }
    i -= N * 32;
    if (i < N * 16)
        reinterpret_cast<float4*>(g_acc)[i] = make_float4(0.f, 0.f, 0.f, 0.f);
}

// ---------------------------------------------------------------------------
// Launch 2: scatter gs(16)+gv(48) per pair via red.global.add.v4 (unchanged)
// ---------------------------------------------------------------------------
__global__ void k_scatter(const int* __restrict__ idxj, const float* __restrict__ gs,
                          const float* __restrict__ gv, int P) {
    long long q = (long long)blockIdx.x * blockDim.x + threadIdx.x;
    long long total = (long long)P * 16;
    if (q >= total) return;
    int p = (int)(q >> 4);
    int c = (int)(q & 15);
    int n = idxj[p];
    float4 v;
    float* dst;
    if (c < 4) {
        v = *reinterpret_cast<const float4*>(gs + (size_t)p * 16 + c * 4);
        dst = g_acc + (size_t)n * 64 + c * 4;
    } else {
        v = *reinterpret_cast<const float4*>(gv + (size_t)p * 48 + (c - 4) * 4);
        dst = g_acc + (size_t)n * 64 + 16 + (c - 4) * 4;
    }
    asm volatile("red.global.add.v4.f32 [%0], {%1,%2,%3,%4};"
                 :: "l"(dst), "f"(v.x), "f"(v.y), "f"(v.z), "f"(v.w)
                 : "memory");
}

// ---------------------------------------------------------------------------
// Launch 3: fused GEMM-M + assemble (unchanged from R6/R7).
// ---------------------------------------------------------------------------
#define XSF 132
#define WSC 520
#define MSF 516
#define OXS 0
#define OSA 4224
#define OWG 6272
#define OWB 8320
#define GA_SMEM (24960 * 4)           // 99840 B

__global__ void __launch_bounds__(256, 2) k_gemm_assemble(
    const float* __restrict__ q, const float* __restrict__ Wgf, int N) {
    extern __shared__ float sm[];
    float* Xs   = sm + OXS;
    float* sa   = sm + OSA;
    float* Wgfs = sm + OWG;
    float* Wb0  = sm + OWB;
    float* Wb1  = sm + OWB + 8320;
    float* Ms   = sm + OWB;
    int a0 = blockIdx.x * 32;
    int tid = threadIdx.x;
    int lane = tid & 31, wn = tid >> 5;
    int gid = lane >> 2, tig = lane & 3;

    for (int i = tid; i < 32 * 32; i += 256) {
        int r = i >> 5, f4 = i & 31;
        int n = a0 + r; if (n >= N) n = N - 1;
        cpa16(Xs + r * XSF + f4 * 4, g_embT + (size_t)n * 128 + f4 * 4);
    }
    for (int i = tid; i < 32 * 16; i += 256) {
        int r = i >> 4, c4 = i & 15;
        int n = a0 + r; if (n >= N) n = N - 1;
        cpa16(sa + r * 64 + c4 * 4, g_acc + (size_t)n * 64 + c4 * 4);
    }
    for (int i = tid; i < 16 * 32; i += 256) {
        cpa16(Wgfs + i * 4, Wgf + i * 4);
    }
    for (int i = tid; i < 16 * 128; i += 256) {
        int r = i >> 7, c4 = i & 127;
        cpa16(Wb0 + r * WSC + c4 * 4, g_aghT + (size_t)r * 512 + c4 * 4);
    }
    CP_COMMIT();
    for (int i = tid; i < 16 * 128; i += 256) {
        int r = i >> 7, c4 = i & 127;
        cpa16(Wb1 + r * WSC + c4 * 4, g_aghT + (size_t)(16 + r) * 512 + c4 * 4);
    }
    CP_COMMIT();

    float acc[2][8][4];
    #pragma unroll
    for (int mt = 0; mt < 2; mt++)
        #pragma unroll
        for (int nt = 0; nt < 8; nt++)
            #pragma unroll
            for (int e = 0; e < 4; e++) acc[mt][nt][e] = 0.f;

    for (int c = 0; c < 8; c++) {
        CP_WAIT1();
        __syncthreads();
        float* wb = (c & 1) ? Wb1 : Wb0;
        #pragma unroll
        for (int ks = 0; ks < 16; ks += 8) {
            int kg = c * 16 + ks;
            uint32_t A[2][4];
            #pragma unroll
            for (int mt = 0; mt < 2; mt++) {
                int row = 16 * mt + gid;
                A[mt][0] = fu(Xs[row * XSF + kg + tig]);
                A[mt][1] = fu(Xs[(row + 8) * XSF + kg + tig]);
                A[mt][2] = fu(Xs[row * XSF + kg + tig + 4]);
                A[mt][3] = fu(Xs[(row + 8) * XSF + kg + tig + 4]);
            }
            #pragma unroll
            for (int nt = 0; nt < 8; nt++) {
                int col = 64 * wn + 8 * nt + gid;
                uint32_t B[2];
                B[0] = fu(wb[(ks + tig) * WSC + col]);
                B[1] = fu(wb[(ks + tig + 4) * WSC + col]);
                mma_tf32(acc[0][nt], A[0], B);
                mma_tf32(acc[1][nt], A[1], B);
            }
        }
        __syncthreads();
        if (c + 2 < 8) {
            float* dst = (c & 1) ? Wb1 : Wb0;
            for (int i = tid; i < 16 * 128; i += 256) {
                int r = i >> 7, c4 = i & 127;
                cpa16(dst + r * WSC + c4 * 4,
                      g_aghT + (size_t)((c + 2) * 16 + r) * 512 + c4 * 4);
            }
        }
        CP_COMMIT();
    }

    #pragma unroll
    for (int mt = 0; mt < 2; mt++) {
        int r0 = 16 * mt + gid;
        #pragma unroll
        for (int nt = 0; nt < 8; nt++) {
            int col = 64 * wn + 8 * nt + 2 * tig;
            *reinterpret_cast<float2*>(&Ms[r0 * MSF + col]) =
                make_float2(acc[mt][nt][0], acc[mt][nt][1]);
            *reinterpret_cast<float2*>(&Ms[(r0 + 8) * MSF + col]) =
                make_float2(acc[mt][nt][2], acc[mt][nt][3]);
        }
    }
    __syncthreads();

    for (int idx = tid; idx < 32 * 128; idx += 256) {
        int r = idx >> 7, f = idx & 127;
        int n = a0 + r;
        if (n >= N) continue;
        float m = 0.f;
        #pragma unroll
        for (int g = 0; g < 16; g++) m += sa[r * 64 + g] * Wgfs[g * 128 + f];
        float* msg = g_msg + (size_t)n * 288;
        msg[f]       = f2tf(Xs[r * XSF + f] * m);
        msg[160 + f] = f2tf(q[n] * m);
    }
    for (int idx = tid; idx < 32 * 32; idx += 256) {
        int r = idx >> 5, h = idx & 31;
        int n = a0 + r;
        if (n >= N) continue;
        float v0 = 0.f, v1 = 0.f, v2 = 0.f;
        #pragma unroll
        for (int g = 0; g < 16; g++) {
            float Mv = Ms[r * MSF + g * 32 + h];
            v0 += sa[r * 64 + 16 + g] * Mv;
            v1 += sa[r * 64 + 32 + g] * Mv;
            v2 += sa[r * 64 + 48 + g] * Mv;
        }
        float sq = v0 * v0 + v1 * v1 + v2 * v2;
        g_msg[(size_t)n * 288 + 128 + h] = (sq > 0.f) ? f2tf(sqrtf(sq)) : 0.f;
    }
}

// ---------------------------------------------------------------------------
// Launch 4 (PROFILED): fused 3-layer MLP, 96 atoms/CTA (weight-traffic
// amortization), 16-row double-buffered cp.async chunks. smem 196608 B.
// ---------------------------------------------------------------------------
#define XSP 292
#define H1P 260
#define H2P 132
#define W1P 264
#define W2P 136
#define W3P 136
#define MATOMS 96
#define MOX 0                          // Xs/H1: 96*292 = 28032
#define MW0 28032
#define MW1 (28032 + 4224)             // 32256
#define MH2 (32256 + 4224)             // 36480
#define MLP_SMEM ((36480 + 96 * 132) * 4)   // 196608 B

__global__ void __launch_bounds__(256, 1) k_mlp_tc(
    const float* __restrict__ b1, const float* __restrict__ b2,
    const float* __restrict__ b3, float* __restrict__ out, int N) {
    extern __shared__ float sm[];
    float* Xs  = sm + MOX;
    float* H1  = sm + MOX;
    float* Wb0 = sm + MW0;
    float* Wb1 = sm + MW1;
    float* H2  = sm + MH2;
    int a0 = blockIdx.x * MATOMS;
    int tid = threadIdx.x;
    int lane = tid & 31, warp = tid >> 5;
    int gid = lane >> 2, tig = lane & 3;

    // prologue: Xs (96x288) + W1 chunk0 -> group0 ; W1 chunk1 -> group1
    for (int i = tid; i < 96 * 72; i += 256) {
        int r = i / 72, k4 = i - r * 72;
        int n = a0 + r; if (n >= N) n = N - 1;
        cpa16(Xs + r * XSP + k4 * 4, g_msg + (size_t)n * 288 + k4 * 4);
    }
    for (int i = tid; i < 16 * 64; i += 256) {
        int r = i >> 6, c4 = i & 63;
        cpa16(Wb0 + r * W1P + c4 * 4, g_w1t + (size_t)r * 256 + c4 * 4);
    }
    CP_COMMIT();
    for (int i = tid; i < 16 * 64; i += 256) {
        int r = i >> 6, c4 = i & 63;
        cpa16(Wb1 + r * W1P + c4 * 4, g_w1t + (size_t)(16 + r) * 256 + c4 * 4);
    }
    CP_COMMIT();

    // ===== Layer 1: 288 -> 256, gelu. Warp = 96 rows (6 mt) x 32 cols (4 nt)
    float acc1[6][4][4];
    #pragma unroll
    for (int mt = 0; mt < 6; mt++)
        #pragma unroll
        for (int nt = 0; nt < 4; nt++)
            #pragma unroll
            for (int e = 0; e < 4; e++) acc1[mt][nt][e] = 0.f;

    for (int c = 0; c < 18; c++) {
        CP_WAIT1();
        __syncthreads();
        float* wb = (c & 1) ? Wb1 : Wb0;
        #pragma unroll
        for (int ks = 0; ks < 16; ks += 8) {
            int kg = c * 16 + ks;
            uint32_t A[6][4];
            #pragma unroll
            for (int mt = 0; mt < 6; mt++) {
                int row = 16 * mt + gid;
                A[mt][0] = fu(Xs[row * XSP + kg + tig]);
                A[mt][1] = fu(Xs[(row + 8) * XSP + kg + tig]);
                A[mt][2] = fu(Xs[row * XSP + kg + tig + 4]);
                A[mt][3] = fu(Xs[(row + 8) * XSP + kg + tig + 4]);
            }
            #pragma unroll
            for (int nt = 0; nt < 4; nt++) {
                int col = 32 * warp + 8 * nt + gid;
                uint32_t B[2];
                B[0] = fu(wb[(ks + tig) * W1P + col]);
                B[1] = fu(wb[(ks + tig + 4) * W1P + col]);
                #pragma unroll
                for (int mt = 0; mt < 6; mt++) mma_tf32(acc1[mt][nt], A[mt], B);
            }
        }
        __syncthreads();
        if (c + 2 < 18) {
            float* dst = (c & 1) ? Wb1 : Wb0;
            for (int i = tid; i < 16 * 64; i += 256) {
                int r = i >> 6, c4 = i & 63;
                cpa16(dst + r * W1P + c4 * 4,
                      g_w1t + (size_t)((c + 2) * 16 + r) * 256 + c4 * 4);
            }
        }
        CP_COMMIT();
    }

    // prefetch W2 chunks 0,1
    for (int i = tid; i < 16 * 32; i += 256) {
        int r = i >> 5, c4 = i & 31;
        cpa16(Wb0 + r * W2P + c4 * 4, g_w2t + (size_t)r * 128 + c4 * 4);
    }
    CP_COMMIT();
    for (int i = tid; i < 16 * 32; i += 256) {
        int r = i >> 5, c4 = i & 31;
        cpa16(Wb1 + r * W2P + c4 * 4, g_w2t + (size_t)(16 + r) * 128 + c4 * 4);
    }
    CP_COMMIT();

    // H1 epilogue (all Xs reads done; overwrite region)
    #pragma unroll
    for (int mt = 0; mt < 6; mt++) {
        int r0 = 16 * mt + gid;
        #pragma unroll
        for (int nt = 0; nt < 4; nt++) {
            int col = 32 * warp + 8 * nt + 2 * tig;
            float bb0 = b1[col], bb1 = b1[col + 1];
            H1[r0 * H1P + col]     = f2tf(gelu_exact(acc1[mt][nt][0] + bb0));
            H1[r0 * H1P + col + 1] = f2tf(gelu_exact(acc1[mt][nt][1] + bb1));
            H1[(r0 + 8) * H1P + col]     = f2tf(gelu_exact(acc1[mt][nt][2] + bb0));
            H1[(r0 + 8) * H1P + col + 1] = f2tf(gelu_exact(acc1[mt][nt][3] + bb1));
        }
    }
    __syncthreads();

    // ===== Layer 2: 256 -> 128, gelu. Warps 2x4: 48 rows (3 mt) x 32 cols (4 nt)
    int wm2 = warp >> 2, wn2 = warp & 3;
    float acc2[3][4][4];
    #pragma unroll
    for (int mt = 0; mt < 3; mt++)
        #pragma unroll
        for (int nt = 0; nt < 4; nt++)
            #pragma unroll
            for (int e = 0; e < 4; e++) acc2[mt][nt][e] = 0.f;

    for (int c = 0; c < 16; c++) {
        CP_WAIT1();
        __syncthreads();
        float* wb = (c & 1) ? Wb1 : Wb0;
        #pragma unroll
        for (int ks = 0; ks < 16; ks += 8) {
            int kg = c * 16 + ks;
            uint32_t A[3][4];
            #pragma unroll
            for (int mt = 0; mt < 3; mt++) {
                int row = 48 * wm2 + 16 * mt + gid;
                A[mt][0] = fu(H1[row * H1P + kg + tig]);
                A[mt][1] = fu(H1[(row + 8) * H1P + kg + tig]);
                A[mt][2] = fu(H1[row * H1P + kg + tig + 4]);
                A[mt][3] = fu(H1[(row + 8) * H1P + kg + tig + 4]);
            }
            #pragma unroll
            for (int nt = 0; nt < 4; nt++) {
                int col = 32 * wn2 + 8 * nt + gid;
                uint32_t B[2];
                B[0] = fu(wb[(ks + tig) * W2P + col]);
                B[1] = fu(wb[(ks + tig + 4) * W2P + col]);
                #pragma unroll
                for (int mt = 0; mt < 3; mt++) mma_tf32(acc2[mt][nt], A[mt], B);
            }
        }
        __syncthreads();
        if (c + 2 < 16) {
            float* dst = (c & 1) ? Wb1 : Wb0;
            for (int i = tid; i < 16 * 32; i += 256) {
                int r = i >> 5, c4 = i & 31;
                cpa16(dst + r * W2P + c4 * 4,
                      g_w2t + (size_t)((c + 2) * 16 + r) * 128 + c4 * 4);
            }
        }
        CP_COMMIT();
    }

    // prefetch W3 chunks 0,1
    for (int i = tid; i < 16 * 34; i += 256) {
        int r = i / 34, c4 = i - r * 34;
        cpa16(Wb0 + r * W3P + c4 * 4, g_w3t + (size_t)r * 136 + c4 * 4);
    }
    CP_COMMIT();
    for (int i = tid; i < 16 * 34; i += 256) {
        int r = i / 34, c4 = i - r * 34;
        cpa16(Wb1 + r * W3P + c4 * 4, g_w3t + (size_t)(16 + r) * 136 + c4 * 4);
    }
    CP_COMMIT();

    // H2 epilogue
    #pragma unroll
    for (int mt = 0; mt < 3; mt++) {
        int r0 = 48 * wm2 + 16 * mt + gid;
        #pragma unroll
        for (int nt = 0; nt < 4; nt++) {
            int col = 32 * wn2 + 8 * nt + 2 * tig;
            float bb0 = b2[col], bb1 = b2[col + 1];
            H2[r0 * H2P + col]     = f2tf(gelu_exact(acc2[mt][nt][0] + bb0));
            H2[r0 * H2P + col + 1] = f2tf(gelu_exact(acc2[mt][nt][1] + bb1));
            H2[(r0 + 8) * H2P + col]     = f2tf(gelu_exact(acc2[mt][nt][2] + bb0));
            H2[(r0 + 8) * H2P + col + 1] = f2tf(gelu_exact(acc2[mt][nt][3] + bb1));
        }
    }
    __syncthreads();

    // ===== Layer 3: 128 -> 130(136). 102 warp-tiles (6m x 17n) over 8 warps
    float d3[13][4];
    #pragma unroll
    for (int tt = 0; tt < 13; tt++)
        #pragma unroll
        for (int e = 0; e < 4; e++) d3[tt][e] = 0.f;

    for (int c = 0; c < 8; c++) {
        CP_WAIT1();
        __syncthreads();
        float* wb = (c & 1) ? Wb1 : Wb0;
        #pragma unroll
        for (int tt = 0; tt < 13; tt++) {
            int t = warp + 8 * tt;
            if (t >= 102) break;
            int m0 = 16 * (t % 6), n0 = 8 * (t / 6);
            #pragma unroll
            for (int ks = 0; ks < 16; ks += 8) {
                int kg = c * 16 + ks;
                uint32_t A[4], B[2];
                A[0] = fu(H2[(m0 + gid) * H2P + kg + tig]);
                A[1] = fu(H2[(m0 + 8 + gid) * H2P + kg + tig]);
                A[2] = fu(H2[(m0 + gid) * H2P + kg + tig + 4]);
                A[3] = fu(H2[(m0 + 8 + gid) * H2P + kg + tig + 4]);
                B[0] = fu(wb[(ks + tig) * W3P + n0 + gid]);
                B[1] = fu(wb[(ks + tig + 4) * W3P + n0 + gid]);
                mma_tf32(d3[tt], A, B);
            }
        }
        __syncthreads();
        if (c + 2 < 8) {
            float* dst = (c & 1) ? Wb1 : Wb0;
            for (int i = tid; i < 16 * 34; i += 256) {
                int r = i / 34, c4 = i - r * 34;
                cpa16(dst + r * W3P + c4 * 4,
                      g_w3t + (size_t)((c + 2) * 16 + r) * 136 + c4 * 4);
            }
        }
        CP_COMMIT();
    }

    // store
    size_t dq_off = (size_t)N * 128;
    size_t f_off = dq_off + (size_t)N;
    #pragma unroll
    for (int tt = 0; tt < 13; tt++) {
        int t = warp + 8 * tt;
        if (t >= 102) break;
        int m0 = 16 * (t % 6), n0 = 8 * (t / 6);
        #pragma unroll
        for (int e = 0; e < 4; e++) {
            int r = m0 + gid + ((e >> 1) ? 8 : 0);
            int j = n0 + 2 * tig + (e & 1);
            int n = a0 + r;
            if (n >= N || j >= 130) continue;
            float v = d3[tt][e] + b3[j];
            if (j == 0)      out[dq_off + n] = v;
            else if (j == 1) out[f_off + n] = v;
            else             out[(size_t)n * 128 + (j - 2)] = v;
        }
    }
}

// ---------------------------------------------------------------------------
extern "C" void kernel_launch(void* const* d_in, const int* in_sizes, int n_in,
                              void* d_out, int out_size) {
    const float* emb  = (const float*)d_in[0];
    const float* q    = (const float*)d_in[1];
    const int*   pidx = (const int*)d_in[2];
    const float* gs   = (const float*)d_in[3];
    const float* gv   = (const float*)d_in[4];
    const float* agh  = (const float*)d_in[5];
    const float* Wgf  = (const float*)d_in[6];
    const float* W1   = (const float*)d_in[7];
    const float* b1   = (const float*)d_in[8];
    const float* W2   = (const float*)d_in[9];
    const float* b2   = (const float*)d_in[10];
    const float* W3   = (const float*)d_in[11];
    const float* b3   = (const float*)d_in[12];
    float* out = (float*)d_out;

    int N = in_sizes[0] / 128;
    int P = in_sizes[2] / 2;
    if (N > NMAX) N = NMAX;
    const int* idxj = pidx + P;

    // 1: tf32 conversion + zero accumulators (merged)
    int cvt_tot = CVT_W + N * 32 + N * 16;
    k_cvt<<<(cvt_tot + 255) / 256, 256>>>(agh, W1, W2, W3, emb, N);

    // 2: pair scatter
    long long Q = (long long)P * 16;
    k_scatter<<<(int)((Q + 255) / 256), 256>>>(idxj, gs, gv, P);

    // 3: fused GEMM-M + assemble
    cudaFuncSetAttribute(k_gemm_assemble, cudaFuncAttributeMaxDynamicSharedMemorySize, GA_SMEM);
    k_gemm_assemble<<<(N + 31) / 32, 256, GA_SMEM>>>(q, Wgf, N);

    // 4 (profiled): fused MLP, 96 atoms/CTA
    cudaFuncSetAttribute(k_mlp_tc, cudaFuncAttributeMaxDynamicSharedMemorySize, MLP_SMEM);
    k_mlp_tc<<<(N + MATOMS - 1) / MATOMS, 256, MLP_SMEM>>>(b1, b2, b3, out, N);
}